// round 2
// baseline (speedup 1.0000x reference)
#include <cuda_runtime.h>
#include <cuda_bf16.h>
#include <cstddef>

// Problem constants
#define BATCH 8
#define SEQ   1024
#define DIM   1024
#define HEADS 16
#define HDIM  64
#define MROWS (BATCH * SEQ)          // 8192
#define QKVN  (3 * DIM)              // 3072
#define SCALE 0.03125f               // DIM^-0.5 = 1/32

// Scratch (static device globals: allocation-free rule)
__device__ float g_q[BATCH * HEADS * SEQ * HDIM];     // [b,h,n,d]
__device__ float g_k[BATCH * HEADS * SEQ * HDIM];
__device__ float g_v[BATCH * HEADS * SEQ * HDIM];
__device__ float g_attn[BATCH * SEQ * DIM];           // [b,n,h*d]

// ---------------------------------------------------------------------------
// Kernel 1: fused QKV projection.
// Y[m, n] = X[m,:] . W[n,:]  where W = concat(W_qk (2048 rows), W_v (1024 rows))
// Epilogue: add pos to q and k, scatter into [b,h,n,d] layout.
// 128x128x16 tile, 256 threads, 8x8 per thread.
// ---------------------------------------------------------------------------
#define GBM 128
#define GBN 128
#define GBK 16
#define GPAD 132   // stride mod 32 == 4 -> mild conflicts only

__global__ __launch_bounds__(256) void qkv_gemm_kernel(
    const float* __restrict__ X, const float* __restrict__ Wqk,
    const float* __restrict__ Wv, const float* __restrict__ pos)
{
    __shared__ float As[GBK][GPAD];
    __shared__ float Bs[GBK][GPAD];

    const int bm = blockIdx.y * GBM;
    const int bn = blockIdx.x * GBN;
    const int tid = threadIdx.x;
    const int tx = tid & 15;       // col group
    const int ty = tid >> 4;       // row group

    float acc[8][8];
#pragma unroll
    for (int i = 0; i < 8; i++)
#pragma unroll
        for (int j = 0; j < 8; j++) acc[i][j] = 0.f;

    for (int k0 = 0; k0 < DIM; k0 += GBK) {
        // Load A tile: X[(bm+m), k0+kk] -> As[kk][m]
#pragma unroll
        for (int i = tid; i < GBM * GBK; i += 256) {
            int m = i >> 4, kk = i & 15;
            As[kk][m] = X[(size_t)(bm + m) * DIM + k0 + kk];
        }
        // Load B tile: W[(bn+n), k0+kk] -> Bs[kk][n]
#pragma unroll
        for (int i = tid; i < GBN * GBK; i += 256) {
            int n = i >> 4, kk = i & 15;
            int gn = bn + n;
            const float* Wrow = (gn < 2 * DIM) ? (Wqk + (size_t)gn * DIM)
                                               : (Wv + (size_t)(gn - 2 * DIM) * DIM);
            Bs[kk][n] = Wrow[k0 + kk];
        }
        __syncthreads();
#pragma unroll
        for (int kk = 0; kk < GBK; kk++) {
            float4 a0 = *(const float4*)&As[kk][ty * 8];
            float4 a1 = *(const float4*)&As[kk][ty * 8 + 4];
            float4 b0 = *(const float4*)&Bs[kk][tx * 8];
            float4 b1 = *(const float4*)&Bs[kk][tx * 8 + 4];
            float a[8] = {a0.x, a0.y, a0.z, a0.w, a1.x, a1.y, a1.z, a1.w};
            float b[8] = {b0.x, b0.y, b0.z, b0.w, b1.x, b1.y, b1.z, b1.w};
#pragma unroll
            for (int i = 0; i < 8; i++)
#pragma unroll
                for (int j = 0; j < 8; j++) acc[i][j] += a[i] * b[j];
        }
        __syncthreads();
    }

    // Epilogue: scatter to q/k/v in [b,h,n,d] layout; q,k get +pos.
#pragma unroll
    for (int i = 0; i < 8; i++) {
        int m = bm + ty * 8 + i;
        int b = m >> 10, row = m & 1023;
#pragma unroll
        for (int j = 0; j < 8; j++) {
            int gn = bn + tx * 8 + j;
            float val = acc[i][j];
            if (gn < DIM) {
                int c = gn, h = c >> 6, d = c & 63;
                val += pos[(size_t)m * DIM + c];
                g_q[(((size_t)b * HEADS + h) * SEQ + row) * HDIM + d] = val;
            } else if (gn < 2 * DIM) {
                int c = gn - DIM, h = c >> 6, d = c & 63;
                val += pos[(size_t)m * DIM + c];
                g_k[(((size_t)b * HEADS + h) * SEQ + row) * HDIM + d] = val;
            } else {
                int c = gn - 2 * DIM, h = c >> 6, d = c & 63;
                g_v[(((size_t)b * HEADS + h) * SEQ + row) * HDIM + d] = val;
            }
        }
    }
}

// ---------------------------------------------------------------------------
// Kernel 2: flash-style attention per (b,h). 64 query rows per block,
// streaming 64-key tiles with online softmax. 256 threads, 4x4 microtiles.
// Mask semantics match reference: score = (m[i] && m[j]) ? s*scale : -FLT_MAX,
// where m is the mask padded with True at position 0.
// Mask input is int32 (harness widens jax bool -> int32).
// ---------------------------------------------------------------------------
#define ATT_SMEM_FLOATS (64*64 /*Q*/ + 64*65 /*K*/ + 64*64 /*V*/ + 64*65 /*P*/ \
                         + 64*17 /*red*/ + 64*5 /*rowm,rowl,rowfac,qm,km*/)
#define ATT_SMEM_BYTES (ATT_SMEM_FLOATS * 4)

__global__ __launch_bounds__(256) void attn_kernel(const int* __restrict__ mask)
{
    extern __shared__ float smem[];
    float* Qs = smem;                       // [64][64]
    float* Ks = Qs + 64 * 64;               // [64][65]
    float* Vs = Ks + 64 * 65;               // [64][64]
    float* Ps = Vs + 64 * 64;               // [64][65]
    float* red = Ps + 64 * 65;              // [64][17]
    float* rowm = red + 64 * 17;
    float* rowl = rowm + 64;
    float* rowfac = rowl + 64;
    float* qm = rowfac + 64;                // 0/1 flags
    float* km = qm + 64;

    const int bh = blockIdx.y;
    const int b = bh >> 4;
    const int i0 = blockIdx.x * 64;
    const int tid = threadIdx.x;
    const int tx = tid & 15;
    const int ty = tid >> 4;
    const float MASKV = -3.402823466e38f;

    const float* qptr = g_q + ((size_t)bh * SEQ + i0) * HDIM;
    const float* kbase = g_k + (size_t)bh * SEQ * HDIM;
    const float* vbase = g_v + (size_t)bh * SEQ * HDIM;

    for (int idx = tid; idx < 64 * 64; idx += 256) {
        int r = idx >> 6, d = idx & 63;
        Qs[r * 64 + d] = qptr[(size_t)r * HDIM + d];
    }
    if (tid < 64) {
        int gi = i0 + tid;
        qm[tid] = (gi == 0) ? 1.f : (mask[(size_t)b * (SEQ - 1) + gi - 1] ? 1.f : 0.f);
        rowm[tid] = -INFINITY;
        rowl[tid] = 0.f;
    }

    float acc[4][4];
#pragma unroll
    for (int r = 0; r < 4; r++)
#pragma unroll
        for (int c = 0; c < 4; c++) acc[r][c] = 0.f;

    for (int j0 = 0; j0 < SEQ; j0 += 64) {
        __syncthreads();  // protect K/V/P reuse (and Q/qm first time)
        for (int idx = tid; idx < 64 * 64; idx += 256) {
            int c = idx >> 6, d = idx & 63;
            Ks[c * 65 + d] = kbase[(size_t)(j0 + c) * HDIM + d];
            Vs[c * 64 + d] = vbase[(size_t)(j0 + c) * HDIM + d];
        }
        if (tid < 64) {
            int gj = j0 + tid;
            km[tid] = (gj == 0) ? 1.f : (mask[(size_t)b * (SEQ - 1) + gj - 1] ? 1.f : 0.f);
        }
        __syncthreads();

        // S = Q . K^T (64x64), 4x4 per thread
        float s[4][4];
#pragma unroll
        for (int r = 0; r < 4; r++)
#pragma unroll
            for (int c = 0; c < 4; c++) s[r][c] = 0.f;
#pragma unroll 4
        for (int d = 0; d < 64; d++) {
            float a[4], bb[4];
#pragma unroll
            for (int r = 0; r < 4; r++) a[r] = Qs[(ty * 4 + r) * 64 + d];
#pragma unroll
            for (int c = 0; c < 4; c++) bb[c] = Ks[(tx * 4 + c) * 65 + d];
#pragma unroll
            for (int r = 0; r < 4; r++)
#pragma unroll
                for (int c = 0; c < 4; c++) s[r][c] += a[r] * bb[c];
        }

        // mask + scale, per-row local max
#pragma unroll
        for (int r = 0; r < 4; r++) {
            int qr = ty * 4 + r;
            bool qok = qm[qr] != 0.f;
            float mx = -INFINITY;
#pragma unroll
            for (int c = 0; c < 4; c++) {
                int kc = tx * 4 + c;
                float val = (qok && km[kc] != 0.f) ? s[r][c] * SCALE : MASKV;
                s[r][c] = val;
                mx = fmaxf(mx, val);
            }
            red[qr * 17 + tx] = mx;
        }
        __syncthreads();

        if (tid < 64) {
            float mx = red[tid * 17];
#pragma unroll
            for (int t = 1; t < 16; t++) mx = fmaxf(mx, red[tid * 17 + t]);
            float nm = fmaxf(rowm[tid], mx);     // nm >= MASKV (finite)
            rowfac[tid] = expf(rowm[tid] - nm);  // exp(-inf)=0 on first tile
            rowm[tid] = nm;
        }
        __syncthreads();

        // P = exp(S - rowmax), staged to smem
#pragma unroll
        for (int r = 0; r < 4; r++) {
            int qr = ty * 4 + r;
            float nm = rowm[qr];
#pragma unroll
            for (int c = 0; c < 4; c++)
                Ps[qr * 65 + tx * 4 + c] = expf(s[r][c] - nm);
        }
        __syncthreads();

        if (tid < 64) {
            float sum = 0.f;
#pragma unroll 8
            for (int c = 0; c < 64; c++) sum += Ps[tid * 65 + c];
            rowl[tid] = rowl[tid] * rowfac[tid] + sum;
        }

        // acc = acc*fac + P @ V
#pragma unroll
        for (int r = 0; r < 4; r++) {
            float f = rowfac[ty * 4 + r];
#pragma unroll
            for (int c = 0; c < 4; c++) acc[r][c] *= f;
        }
#pragma unroll 4
        for (int c = 0; c < 64; c++) {
            float4 vv = *(const float4*)&Vs[c * 64 + tx * 4];
#pragma unroll
            for (int r = 0; r < 4; r++) {
                float p = Ps[(ty * 4 + r) * 65 + c];
                acc[r][0] += p * vv.x;
                acc[r][1] += p * vv.y;
                acc[r][2] += p * vv.z;
                acc[r][3] += p * vv.w;
            }
        }
    }
    __syncthreads();

    // normalize and write in [b, n, h*64+d] layout for the output GEMM
    const int h = bh & 15;
#pragma unroll
    for (int r = 0; r < 4; r++) {
        int qr = ty * 4 + r;
        float inv = 1.f / rowl[qr];
        int gi = i0 + qr;
        float* op = g_attn + ((size_t)b * SEQ + gi) * DIM + h * HDIM + tx * 4;
#pragma unroll
        for (int c = 0; c < 4; c++) op[c] = acc[r][c] * inv;
    }
}

// ---------------------------------------------------------------------------
// Kernel 3: output projection. out = g_attn @ W_out^T + b_out
// ---------------------------------------------------------------------------
__global__ __launch_bounds__(256) void out_gemm_kernel(
    const float* __restrict__ Wout, const float* __restrict__ bout,
    float* __restrict__ out)
{
    __shared__ float As[GBK][GPAD];
    __shared__ float Bs[GBK][GPAD];

    const int bm = blockIdx.y * GBM;
    const int bn = blockIdx.x * GBN;
    const int tid = threadIdx.x;
    const int tx = tid & 15;
    const int ty = tid >> 4;

    float acc[8][8];
#pragma unroll
    for (int i = 0; i < 8; i++)
#pragma unroll
        for (int j = 0; j < 8; j++) acc[i][j] = 0.f;

    for (int k0 = 0; k0 < DIM; k0 += GBK) {
#pragma unroll
        for (int i = tid; i < GBM * GBK; i += 256) {
            int m = i >> 4, kk = i & 15;
            As[kk][m] = g_attn[(size_t)(bm + m) * DIM + k0 + kk];
        }
#pragma unroll
        for (int i = tid; i < GBN * GBK; i += 256) {
            int n = i >> 4, kk = i & 15;
            Bs[kk][n] = Wout[(size_t)(bn + n) * DIM + k0 + kk];
        }
        __syncthreads();
#pragma unroll
        for (int kk = 0; kk < GBK; kk++) {
            float4 a0 = *(const float4*)&As[kk][ty * 8];
            float4 a1 = *(const float4*)&As[kk][ty * 8 + 4];
            float4 b0 = *(const float4*)&Bs[kk][tx * 8];
            float4 b1 = *(const float4*)&Bs[kk][tx * 8 + 4];
            float a[8] = {a0.x, a0.y, a0.z, a0.w, a1.x, a1.y, a1.z, a1.w};
            float b[8] = {b0.x, b0.y, b0.z, b0.w, b1.x, b1.y, b1.z, b1.w};
#pragma unroll
            for (int i = 0; i < 8; i++)
#pragma unroll
                for (int j = 0; j < 8; j++) acc[i][j] += a[i] * b[j];
        }
        __syncthreads();
    }

#pragma unroll
    for (int i = 0; i < 8; i++) {
        int m = bm + ty * 8 + i;
#pragma unroll
        for (int j = 0; j < 8; j++) {
            int gn = bn + tx * 8 + j;
            out[(size_t)m * DIM + gn] = acc[i][j] + bout[gn];
        }
    }
}

// ---------------------------------------------------------------------------
extern "C" void kernel_launch(void* const* d_in, const int* in_sizes, int n_in,
                              void* d_out, int out_size)
{
    const float* x    = (const float*)d_in[0];
    const int*   mask = (const int*)d_in[1];     // bool widened to int32 by harness
    const float* pos  = (const float*)d_in[2];
    const float* Wqk  = (const float*)d_in[3];
    const float* Wv   = (const float*)d_in[4];
    const float* Wout = (const float*)d_in[5];
    const float* bout = (const float*)d_in[6];
    float*       out  = (float*)d_out;

    cudaFuncSetAttribute(attn_kernel, cudaFuncAttributeMaxDynamicSharedMemorySize,
                         ATT_SMEM_BYTES);

    {   // QKV projection: M=8192, N=3072
        dim3 grid(QKVN / GBN, MROWS / GBM);
        qkv_gemm_kernel<<<grid, 256>>>(x, Wqk, Wv, pos);
    }
    {   // Attention: 16 row-tiles x 128 (b,h) pairs
        dim3 grid(SEQ / 64, BATCH * HEADS);
        attn_kernel<<<grid, 256, ATT_SMEM_BYTES>>>(mask);
    }
    {   // Output projection: M=8192, N=1024
        dim3 grid(DIM / GBN, MROWS / GBM);
        out_gemm_kernel<<<grid, 256>>>(Wout, bout, out);
    }
}

// round 3
// speedup vs baseline: 1.4326x; 1.4326x over previous
#include <cuda_runtime.h>
#include <cuda_bf16.h>
#include <cstddef>
#include <cstdint>

// Problem constants
#define BATCH 8
#define SEQ   1024
#define DIM   1024
#define HEADS 16
#define HDIM  64
#define MROWS (BATCH * SEQ)          // 8192
#define QKVN  (3 * DIM)              // 3072
#define SCALE 0.03125f               // DIM^-0.5 = 1/32

// Scratch (static device globals: allocation-free rule)
__device__ float g_q[BATCH * HEADS * SEQ * HDIM];     // [b,h,n,d]
__device__ float g_k[BATCH * HEADS * SEQ * HDIM];
__device__ float g_v[BATCH * HEADS * SEQ * HDIM];
__device__ float g_attn[BATCH * SEQ * DIM];           // [b,n,h*d]

// ---------------------------------------------------------------------------
// tf32 helpers
// ---------------------------------------------------------------------------
__device__ __forceinline__ float tf32_rna(float x) {
    uint32_t u;
    asm("cvt.rna.tf32.f32 %0, %1;" : "=r"(u) : "f"(x));
    return __uint_as_float(u);
}

__device__ __forceinline__ void mma_tf32_16x8x8(float* c, const float* a, const float* b) {
    asm volatile(
        "mma.sync.aligned.m16n8k8.row.col.f32.tf32.tf32.f32 "
        "{%0,%1,%2,%3}, {%4,%5,%6,%7}, {%8,%9}, {%0,%1,%2,%3};"
        : "+f"(c[0]), "+f"(c[1]), "+f"(c[2]), "+f"(c[3])
        : "r"(__float_as_uint(a[0])), "r"(__float_as_uint(a[1])),
          "r"(__float_as_uint(a[2])), "r"(__float_as_uint(a[3])),
          "r"(__float_as_uint(b[0])), "r"(__float_as_uint(b[1])));
}

// ---------------------------------------------------------------------------
// tf32 tensor-core GEMM core: 128x128 block tile, K-tile 32, 256 threads.
// 8 warps in 2(M) x 4(N) arrangement; each warp computes 64x32 via
// 4x4 m16n8k8 tiles. Smem tiles stored [row][k] with +4 padding so that
// fragment loads (addr = 36*row + k) are bank-conflict-free.
// ---------------------------------------------------------------------------
#define TPAD 36   // 32 + 4

struct GemmAcc {
    float acc[4][4][4];   // [mi][ni][reg]
};

// Computes the 128x128 accumulator for A[bm..][*] . B[bn..][*]^T where
// rows of A come from loadA and rows of B from loadB (both row-major, K=1024).
// As/Bs shared tiles must be provided by caller.
__device__ __forceinline__ void gemm_tf32_core(
    const float* __restrict__ Abase,   // [M][1024] row-major, row bm already applied by caller
    const float* __restrict__ B0,      // W_qk or W_out (row-major [*, 1024])
    const float* __restrict__ B1,      // W_v (or nullptr); rows >= 2048 come from here
    int bm, int bn, bool splitB,
    float (*As)[TPAD], float (*Bs)[TPAD], GemmAcc& g)
{
    const int tid = threadIdx.x;
    const int lane = tid & 31;
    const int wid = tid >> 5;
    const int gid = lane >> 2;    // 0..7
    const int tg = lane & 3;      // 0..3
    const int wm = (wid & 1) * 64;
    const int wn = (wid >> 1) * 32;

#pragma unroll
    for (int mi = 0; mi < 4; mi++)
#pragma unroll
        for (int ni = 0; ni < 4; ni++)
#pragma unroll
            for (int r = 0; r < 4; r++) g.acc[mi][ni][r] = 0.f;

    for (int k0 = 0; k0 < DIM; k0 += 32) {
        // Load A tile: 128 rows x 32 cols = 128x8 float4, 256 threads -> 4 each
#pragma unroll
        for (int i = tid; i < 128 * 8; i += 256) {
            int row = i >> 3, c4 = (i & 7) * 4;
            const float4 v = *(const float4*)&Abase[(size_t)(bm + row) * DIM + k0 + c4];
            As[row][c4 + 0] = tf32_rna(v.x);
            As[row][c4 + 1] = tf32_rna(v.y);
            As[row][c4 + 2] = tf32_rna(v.z);
            As[row][c4 + 3] = tf32_rna(v.w);
        }
        // Load B tile
#pragma unroll
        for (int i = tid; i < 128 * 8; i += 256) {
            int row = i >> 3, c4 = (i & 7) * 4;
            int gn = bn + row;
            const float* Brow;
            if (splitB && gn >= 2 * DIM) Brow = B1 + (size_t)(gn - 2 * DIM) * DIM;
            else                          Brow = B0 + (size_t)gn * DIM;
            const float4 v = *(const float4*)&Brow[k0 + c4];
            Bs[row][c4 + 0] = tf32_rna(v.x);
            Bs[row][c4 + 1] = tf32_rna(v.y);
            Bs[row][c4 + 2] = tf32_rna(v.z);
            Bs[row][c4 + 3] = tf32_rna(v.w);
        }
        __syncthreads();

#pragma unroll
        for (int ks = 0; ks < 32; ks += 8) {
            float a[4][4];
#pragma unroll
            for (int mi = 0; mi < 4; mi++) {
                int r0 = wm + mi * 16 + gid;
                a[mi][0] = As[r0][ks + tg];
                a[mi][1] = As[r0 + 8][ks + tg];
                a[mi][2] = As[r0][ks + tg + 4];
                a[mi][3] = As[r0 + 8][ks + tg + 4];
            }
            float b[4][2];
#pragma unroll
            for (int ni = 0; ni < 4; ni++) {
                int n0 = wn + ni * 8 + gid;
                b[ni][0] = Bs[n0][ks + tg];
                b[ni][1] = Bs[n0][ks + tg + 4];
            }
#pragma unroll
            for (int mi = 0; mi < 4; mi++)
#pragma unroll
                for (int ni = 0; ni < 4; ni++)
                    mma_tf32_16x8x8(g.acc[mi][ni], a[mi], b[ni]);
        }
        __syncthreads();
    }
}

// ---------------------------------------------------------------------------
// Kernel 1: fused QKV projection (tf32 tensor cores).
// Y[m, n] = X[m,:] . W[n,:], W = concat(W_qk (2048 rows), W_v (1024 rows)).
// Epilogue: add pos to q,k; scatter to [b,h,n,d].
// ---------------------------------------------------------------------------
__global__ __launch_bounds__(256) void qkv_gemm_kernel(
    const float* __restrict__ X, const float* __restrict__ Wqk,
    const float* __restrict__ Wv, const float* __restrict__ pos)
{
    __shared__ float As[128][TPAD];
    __shared__ float Bs[128][TPAD];

    const int bm = blockIdx.y * 128;
    const int bn = blockIdx.x * 128;
    const int lane = threadIdx.x & 31;
    const int wid = threadIdx.x >> 5;
    const int gid = lane >> 2, tg = lane & 3;
    const int wm = (wid & 1) * 64;
    const int wn = (wid >> 1) * 32;

    GemmAcc g;
    gemm_tf32_core(X, Wqk, Wv, bm, bn, true, As, Bs, g);

    // Epilogue: scatter to q/k/v in [b,h,n,d] layout; q,k get +pos.
#pragma unroll
    for (int mi = 0; mi < 4; mi++) {
#pragma unroll
        for (int ni = 0; ni < 4; ni++) {
#pragma unroll
            for (int r = 0; r < 4; r++) {
                int m = bm + wm + mi * 16 + gid + ((r >= 2) ? 8 : 0);
                int gn = bn + wn + ni * 8 + 2 * tg + (r & 1);
                int b = m >> 10, row = m & 1023;
                float val = g.acc[mi][ni][r];
                if (gn < DIM) {
                    int c = gn, h = c >> 6, d = c & 63;
                    val += pos[(size_t)m * DIM + c];
                    g_q[(((size_t)b * HEADS + h) * SEQ + row) * HDIM + d] = val;
                } else if (gn < 2 * DIM) {
                    int c = gn - DIM, h = c >> 6, d = c & 63;
                    val += pos[(size_t)m * DIM + c];
                    g_k[(((size_t)b * HEADS + h) * SEQ + row) * HDIM + d] = val;
                } else {
                    int c = gn - 2 * DIM, h = c >> 6, d = c & 63;
                    g_v[(((size_t)b * HEADS + h) * SEQ + row) * HDIM + d] = val;
                }
            }
        }
    }
}

// ---------------------------------------------------------------------------
// Kernel 3: output projection (tf32 tensor cores). out = g_attn @ W_out^T + b
// ---------------------------------------------------------------------------
__global__ __launch_bounds__(256) void out_gemm_kernel(
    const float* __restrict__ Wout, const float* __restrict__ bout,
    float* __restrict__ out)
{
    __shared__ float As[128][TPAD];
    __shared__ float Bs[128][TPAD];

    const int bm = blockIdx.y * 128;
    const int bn = blockIdx.x * 128;
    const int lane = threadIdx.x & 31;
    const int wid = threadIdx.x >> 5;
    const int gid = lane >> 2, tg = lane & 3;
    const int wm = (wid & 1) * 64;
    const int wn = (wid >> 1) * 32;

    GemmAcc g;
    gemm_tf32_core(g_attn, Wout, nullptr, bm, bn, false, As, Bs, g);

#pragma unroll
    for (int mi = 0; mi < 4; mi++) {
#pragma unroll
        for (int ni = 0; ni < 4; ni++) {
#pragma unroll
            for (int r = 0; r < 4; r++) {
                int m = bm + wm + mi * 16 + gid + ((r >= 2) ? 8 : 0);
                int gn = bn + wn + ni * 8 + 2 * tg + (r & 1);
                out[(size_t)m * DIM + gn] = g.acc[mi][ni][r] + bout[gn];
            }
        }
    }
}

// ---------------------------------------------------------------------------
// Kernel 2: flash-style attention per (b,h). Unchanged fp32 SIMT this round.
// ---------------------------------------------------------------------------
#define ATT_SMEM_FLOATS (64*64 /*Q*/ + 64*65 /*K*/ + 64*64 /*V*/ + 64*65 /*P*/ \
                         + 64*17 /*red*/ + 64*5 /*rowm,rowl,rowfac,qm,km*/)
#define ATT_SMEM_BYTES (ATT_SMEM_FLOATS * 4)

__global__ __launch_bounds__(256) void attn_kernel(const int* __restrict__ mask)
{
    extern __shared__ float smem[];
    float* Qs = smem;                       // [64][64]
    float* Ks = Qs + 64 * 64;               // [64][65]
    float* Vs = Ks + 64 * 65;               // [64][64]
    float* Ps = Vs + 64 * 64;               // [64][65]
    float* red = Ps + 64 * 65;              // [64][17]
    float* rowm = red + 64 * 17;
    float* rowl = rowm + 64;
    float* rowfac = rowl + 64;
    float* qm = rowfac + 64;                // 0/1 flags
    float* km = qm + 64;

    const int bh = blockIdx.y;
    const int b = bh >> 4;
    const int i0 = blockIdx.x * 64;
    const int tid = threadIdx.x;
    const int tx = tid & 15;
    const int ty = tid >> 4;
    const float MASKV = -3.402823466e38f;

    const float* qptr = g_q + ((size_t)bh * SEQ + i0) * HDIM;
    const float* kbase = g_k + (size_t)bh * SEQ * HDIM;
    const float* vbase = g_v + (size_t)bh * SEQ * HDIM;

    for (int idx = tid; idx < 64 * 64; idx += 256) {
        int r = idx >> 6, d = idx & 63;
        Qs[r * 64 + d] = qptr[(size_t)r * HDIM + d];
    }
    if (tid < 64) {
        int gi = i0 + tid;
        qm[tid] = (gi == 0) ? 1.f : (mask[(size_t)b * (SEQ - 1) + gi - 1] ? 1.f : 0.f);
        rowm[tid] = -INFINITY;
        rowl[tid] = 0.f;
    }

    float acc[4][4];
#pragma unroll
    for (int r = 0; r < 4; r++)
#pragma unroll
        for (int c = 0; c < 4; c++) acc[r][c] = 0.f;

    for (int j0 = 0; j0 < SEQ; j0 += 64) {
        __syncthreads();  // protect K/V/P reuse (and Q/qm first time)
        for (int idx = tid; idx < 64 * 64; idx += 256) {
            int c = idx >> 6, d = idx & 63;
            Ks[c * 65 + d] = kbase[(size_t)(j0 + c) * HDIM + d];
            Vs[c * 64 + d] = vbase[(size_t)(j0 + c) * HDIM + d];
        }
        if (tid < 64) {
            int gj = j0 + tid;
            km[tid] = (gj == 0) ? 1.f : (mask[(size_t)b * (SEQ - 1) + gj - 1] ? 1.f : 0.f);
        }
        __syncthreads();

        // S = Q . K^T (64x64), 4x4 per thread
        float s[4][4];
#pragma unroll
        for (int r = 0; r < 4; r++)
#pragma unroll
            for (int c = 0; c < 4; c++) s[r][c] = 0.f;
#pragma unroll 4
        for (int d = 0; d < 64; d++) {
            float a[4], bb[4];
#pragma unroll
            for (int r = 0; r < 4; r++) a[r] = Qs[(ty * 4 + r) * 64 + d];
#pragma unroll
            for (int c = 0; c < 4; c++) bb[c] = Ks[(tx * 4 + c) * 65 + d];
#pragma unroll
            for (int r = 0; r < 4; r++)
#pragma unroll
                for (int c = 0; c < 4; c++) s[r][c] += a[r] * bb[c];
        }

        // mask + scale, per-row local max
#pragma unroll
        for (int r = 0; r < 4; r++) {
            int qr = ty * 4 + r;
            bool qok = qm[qr] != 0.f;
            float mx = -INFINITY;
#pragma unroll
            for (int c = 0; c < 4; c++) {
                int kc = tx * 4 + c;
                float val = (qok && km[kc] != 0.f) ? s[r][c] * SCALE : MASKV;
                s[r][c] = val;
                mx = fmaxf(mx, val);
            }
            red[qr * 17 + tx] = mx;
        }
        __syncthreads();

        if (tid < 64) {
            float mx = red[tid * 17];
#pragma unroll
            for (int t = 1; t < 16; t++) mx = fmaxf(mx, red[tid * 17 + t]);
            float nm = fmaxf(rowm[tid], mx);     // nm >= MASKV (finite)
            rowfac[tid] = expf(rowm[tid] - nm);  // exp(-inf)=0 on first tile
            rowm[tid] = nm;
        }
        __syncthreads();

        // P = exp(S - rowmax), staged to smem
#pragma unroll
        for (int r = 0; r < 4; r++) {
            int qr = ty * 4 + r;
            float nm = rowm[qr];
#pragma unroll
            for (int c = 0; c < 4; c++)
                Ps[qr * 65 + tx * 4 + c] = expf(s[r][c] - nm);
        }
        __syncthreads();

        if (tid < 64) {
            float sum = 0.f;
#pragma unroll 8
            for (int c = 0; c < 64; c++) sum += Ps[tid * 65 + c];
            rowl[tid] = rowl[tid] * rowfac[tid] + sum;
        }

        // acc = acc*fac + P @ V
#pragma unroll
        for (int r = 0; r < 4; r++) {
            float f = rowfac[ty * 4 + r];
#pragma unroll
            for (int c = 0; c < 4; c++) acc[r][c] *= f;
        }
#pragma unroll 4
        for (int c = 0; c < 64; c++) {
            float4 vv = *(const float4*)&Vs[c * 64 + tx * 4];
#pragma unroll
            for (int r = 0; r < 4; r++) {
                float p = Ps[(ty * 4 + r) * 65 + c];
                acc[r][0] += p * vv.x;
                acc[r][1] += p * vv.y;
                acc[r][2] += p * vv.z;
                acc[r][3] += p * vv.w;
            }
        }
    }
    __syncthreads();

    // normalize and write in [b, n, h*64+d] layout for the output GEMM
    const int h = bh & 15;
#pragma unroll
    for (int r = 0; r < 4; r++) {
        int qr = ty * 4 + r;
        float inv = 1.f / rowl[qr];
        int gi = i0 + qr;
        float* op = g_attn + ((size_t)b * SEQ + gi) * DIM + h * HDIM + tx * 4;
#pragma unroll
        for (int c = 0; c < 4; c++) op[c] = acc[r][c] * inv;
    }
}

// ---------------------------------------------------------------------------
extern "C" void kernel_launch(void* const* d_in, const int* in_sizes, int n_in,
                              void* d_out, int out_size)
{
    const float* x    = (const float*)d_in[0];
    const int*   mask = (const int*)d_in[1];     // bool widened to int32 by harness
    const float* pos  = (const float*)d_in[2];
    const float* Wqk  = (const float*)d_in[3];
    const float* Wv   = (const float*)d_in[4];
    const float* Wout = (const float*)d_in[5];
    const float* bout = (const float*)d_in[6];
    float*       out  = (float*)d_out;

    cudaFuncSetAttribute(attn_kernel, cudaFuncAttributeMaxDynamicSharedMemorySize,
                         ATT_SMEM_BYTES);

    {   // QKV projection: M=8192, N=3072
        dim3 grid(QKVN / 128, MROWS / 128);
        qkv_gemm_kernel<<<grid, 256>>>(x, Wqk, Wv, pos);
    }
    {   // Attention: 16 row-tiles x 128 (b,h) pairs
        dim3 grid(SEQ / 64, BATCH * HEADS);
        attn_kernel<<<grid, 256, ATT_SMEM_BYTES>>>(mask);
    }
    {   // Output projection: M=8192, N=1024
        dim3 grid(DIM / 128, MROWS / 128);
        out_gemm_kernel<<<grid, 256>>>(Wout, bout, out);
    }
}

// round 4
// speedup vs baseline: 3.4292x; 2.3937x over previous
#include <cuda_runtime.h>
#include <cuda_bf16.h>
#include <cstddef>
#include <cstdint>

// Problem constants
#define BATCH 8
#define SEQ   1024
#define DIM   1024
#define HEADS 16
#define HDIM  64
#define MROWS (BATCH * SEQ)          // 8192
#define QKVN  (3 * DIM)              // 3072
#define SCALE 0.03125f               // DIM^-0.5 = 1/32
#define MASKV (-3.402823466e38f)
#define NEGINF (-__int_as_float(0x7f800000) * 1.0f)

// Scratch (static device globals: allocation-free rule)
__device__ float g_q[BATCH * HEADS * SEQ * HDIM];     // [b,h,n,d]  (tf32-rounded)
__device__ float g_k[BATCH * HEADS * SEQ * HDIM];
__device__ float g_v[BATCH * HEADS * SEQ * HDIM];
__device__ float g_attn[BATCH * SEQ * DIM];           // [b,n,h*d]  (tf32-rounded)
// tf32-rounded input copies (rounding hoisted out of GEMM hot loops)
__device__ float g_xr[MROWS * DIM];
__device__ float g_wqkr[2 * DIM * DIM];
__device__ float g_wvr[DIM * DIM];
__device__ float g_woutr[DIM * DIM];

// ---------------------------------------------------------------------------
// helpers
// ---------------------------------------------------------------------------
__device__ __forceinline__ float tf32_rna(float x) {
    uint32_t u;
    asm("cvt.rna.tf32.f32 %0, %1;" : "=r"(u) : "f"(x));
    return __uint_as_float(u);
}

__device__ __forceinline__ void mma_tf32_16x8x8(float* c, const float* a, const float* b) {
    asm volatile(
        "mma.sync.aligned.m16n8k8.row.col.f32.tf32.tf32.f32 "
        "{%0,%1,%2,%3}, {%4,%5,%6,%7}, {%8,%9}, {%0,%1,%2,%3};"
        : "+f"(c[0]), "+f"(c[1]), "+f"(c[2]), "+f"(c[3])
        : "r"(__float_as_uint(a[0])), "r"(__float_as_uint(a[1])),
          "r"(__float_as_uint(a[2])), "r"(__float_as_uint(a[3])),
          "r"(__float_as_uint(b[0])), "r"(__float_as_uint(b[1])));
}

__device__ __forceinline__ void cp16(void* smem, const void* g) {
    uint32_t s = (uint32_t)__cvta_generic_to_shared(smem);
    asm volatile("cp.async.cg.shared.global [%0], [%1], 16;" :: "r"(s), "l"(g));
}
__device__ __forceinline__ void cp_commit() {
    asm volatile("cp.async.commit_group;");
}

// ---------------------------------------------------------------------------
// Kernel 0: round fp32 -> tf32-valued fp32 (vectorized)
// ---------------------------------------------------------------------------
__global__ __launch_bounds__(256) void round_kernel(
    const float4* __restrict__ src, float4* __restrict__ dst, int n4)
{
    int i = blockIdx.x * 256 + threadIdx.x;
    if (i < n4) {
        float4 v = src[i];
        v.x = tf32_rna(v.x); v.y = tf32_rna(v.y);
        v.z = tf32_rna(v.z); v.w = tf32_rna(v.w);
        dst[i] = v;
    }
}

// ---------------------------------------------------------------------------
// tf32 GEMM core, cp.async 2-stage pipeline. 128x128 tile, K-tile 32,
// 256 threads, 8 warps (2M x 4N), warp tile 64x32 via m16n8k8.
// Inputs must already be tf32-valued.
// ---------------------------------------------------------------------------
#define TPAD 36   // row stride 144 B (16B-aligned, bank-permuting)

struct GemmAcc { float acc[4][4][4]; };

__device__ __forceinline__ void gemm_core_async(
    const float* __restrict__ Abase, const float* __restrict__ B0,
    const float* __restrict__ B1, int bm, int bn, bool splitB,
    float* sm, GemmAcc& g)
{
    // layout: As[2][128][TPAD], Bs[2][128][TPAD]
    float (*As)[128][TPAD] = (float(*)[128][TPAD])sm;
    float (*Bs)[128][TPAD] = (float(*)[128][TPAD])(sm + 2 * 128 * TPAD);

    const int tid = threadIdx.x;
    const int lane = tid & 31;
    const int wid = tid >> 5;
    const int gid = lane >> 2, tg = lane & 3;
    const int wm = (wid & 1) * 64;
    const int wn = (wid >> 1) * 32;

#pragma unroll
    for (int mi = 0; mi < 4; mi++)
#pragma unroll
        for (int ni = 0; ni < 4; ni++)
#pragma unroll
            for (int r = 0; r < 4; r++) g.acc[mi][ni][r] = 0.f;

    auto load_tiles = [&](int st, int k0) {
#pragma unroll
        for (int i = tid; i < 128 * 8; i += 256) {
            int row = i >> 3, c4 = (i & 7) * 4;
            cp16(&As[st][row][c4], &Abase[(size_t)(bm + row) * DIM + k0 + c4]);
        }
#pragma unroll
        for (int i = tid; i < 128 * 8; i += 256) {
            int row = i >> 3, c4 = (i & 7) * 4;
            int gn = bn + row;
            const float* Brow = (splitB && gn >= 2 * DIM)
                                ? B1 + (size_t)(gn - 2 * DIM) * DIM
                                : B0 + (size_t)gn * DIM;
            cp16(&Bs[st][row][c4], &Brow[k0 + c4]);
        }
    };

    load_tiles(0, 0);
    cp_commit();

    const int NT = DIM / 32;  // 32
    for (int it = 0; it < NT; it++) {
        int cur = it & 1;
        if (it + 1 < NT) {
            load_tiles(cur ^ 1, (it + 1) * 32);
            cp_commit();
            asm volatile("cp.async.wait_group 1;");
        } else {
            asm volatile("cp.async.wait_group 0;");
        }
        __syncthreads();

#pragma unroll
        for (int ks = 0; ks < 32; ks += 8) {
            float a[4][4];
#pragma unroll
            for (int mi = 0; mi < 4; mi++) {
                int r0 = wm + mi * 16 + gid;
                a[mi][0] = As[cur][r0][ks + tg];
                a[mi][1] = As[cur][r0 + 8][ks + tg];
                a[mi][2] = As[cur][r0][ks + tg + 4];
                a[mi][3] = As[cur][r0 + 8][ks + tg + 4];
            }
            float b[4][2];
#pragma unroll
            for (int ni = 0; ni < 4; ni++) {
                int n0 = wn + ni * 8 + gid;
                b[ni][0] = Bs[cur][n0][ks + tg];
                b[ni][1] = Bs[cur][n0][ks + tg + 4];
            }
#pragma unroll
            for (int mi = 0; mi < 4; mi++)
#pragma unroll
                for (int ni = 0; ni < 4; ni++)
                    mma_tf32_16x8x8(g.acc[mi][ni], a[mi], b[ni]);
        }
        __syncthreads();
    }
}

#define GEMM_SMEM_BYTES (4 * 128 * TPAD * 4)   // 73728

// ---------------------------------------------------------------------------
// Kernel 1: fused QKV projection. Epilogue adds pos (fp32), rounds result to
// tf32 (feeds attention MMAs), scatters to [b,h,n,d].
// ---------------------------------------------------------------------------
__global__ __launch_bounds__(256) void qkv_gemm_kernel(const float* __restrict__ pos)
{
    extern __shared__ float sm[];
    const int bm = blockIdx.y * 128;
    const int bn = blockIdx.x * 128;
    const int lane = threadIdx.x & 31;
    const int wid = threadIdx.x >> 5;
    const int gid = lane >> 2, tg = lane & 3;
    const int wm = (wid & 1) * 64;
    const int wn = (wid >> 1) * 32;

    GemmAcc g;
    gemm_core_async(g_xr, g_wqkr, g_wvr, bm, bn, true, sm, g);

#pragma unroll
    for (int mi = 0; mi < 4; mi++) {
#pragma unroll
        for (int ni = 0; ni < 4; ni++) {
#pragma unroll
            for (int r = 0; r < 4; r++) {
                int m = bm + wm + mi * 16 + gid + ((r >= 2) ? 8 : 0);
                int gn = bn + wn + ni * 8 + 2 * tg + (r & 1);
                int b = m >> 10, row = m & 1023;
                float val = g.acc[mi][ni][r];
                if (gn < DIM) {
                    int c = gn, h = c >> 6, d = c & 63;
                    val = tf32_rna(val + pos[(size_t)m * DIM + c]);
                    g_q[(((size_t)b * HEADS + h) * SEQ + row) * HDIM + d] = val;
                } else if (gn < 2 * DIM) {
                    int c = gn - DIM, h = c >> 6, d = c & 63;
                    val = tf32_rna(val + pos[(size_t)m * DIM + c]);
                    g_k[(((size_t)b * HEADS + h) * SEQ + row) * HDIM + d] = val;
                } else {
                    int c = gn - 2 * DIM, h = c >> 6, d = c & 63;
                    g_v[(((size_t)b * HEADS + h) * SEQ + row) * HDIM + d] = tf32_rna(val);
                }
            }
        }
    }
}

// ---------------------------------------------------------------------------
// Kernel 3: output projection. out = g_attn @ W_out^T + b_out (fp32 epilogue)
// ---------------------------------------------------------------------------
__global__ __launch_bounds__(256) void out_gemm_kernel(
    const float* __restrict__ bout, float* __restrict__ out)
{
    extern __shared__ float sm[];
    const int bm = blockIdx.y * 128;
    const int bn = blockIdx.x * 128;
    const int lane = threadIdx.x & 31;
    const int wid = threadIdx.x >> 5;
    const int gid = lane >> 2, tg = lane & 3;
    const int wm = (wid & 1) * 64;
    const int wn = (wid >> 1) * 32;

    GemmAcc g;
    gemm_core_async(g_attn, g_woutr, nullptr, bm, bn, false, sm, g);

#pragma unroll
    for (int mi = 0; mi < 4; mi++) {
#pragma unroll
        for (int ni = 0; ni < 4; ni++) {
#pragma unroll
            for (int r = 0; r < 4; r++) {
                int m = bm + wm + mi * 16 + gid + ((r >= 2) ? 8 : 0);
                int gn = bn + wn + ni * 8 + 2 * tg + (r & 1);
                out[(size_t)m * DIM + gn] = g.acc[mi][ni][r] + bout[gn];
            }
        }
    }
}

// ---------------------------------------------------------------------------
// Kernel 2: tensor-core flash attention. 128 query rows per CTA, 8 warps;
// each warp owns 16 rows. j-tiles of 64 keys. Q fragments register-resident.
// S and PV via m16n8k8 tf32. Online softmax in registers (quad shfl reduce).
// P staged through smem overlaid on the (dead) Q tile: warp w reuses exactly
// its own Q rows [16w,16w+16), so no cross-warp race.
// ---------------------------------------------------------------------------
#define APAD 68
#define ATT_SMEM_FLOATS (128 * APAD + 64 * APAD + 64 * APAD + 64)
#define ATT_SMEM_BYTES  (ATT_SMEM_FLOATS * 4)

__global__ __launch_bounds__(256) void attn_kernel(const int* __restrict__ mask)
{
    extern __shared__ float sm[];
    float (*QP)[APAD] = (float(*)[APAD])sm;                    // Q tile, later P
    float (*Ks)[APAD] = (float(*)[APAD])(sm + 128 * APAD);
    float (*Vs)[APAD] = (float(*)[APAD])(sm + 192 * APAD);
    float* km = sm + 256 * APAD;

    const int bh = blockIdx.y;
    const int b = bh >> 4, h = bh & 15;
    const int i0 = blockIdx.x * 128;
    const int tid = threadIdx.x;
    const int lane = tid & 31, wid = tid >> 5;
    const int gid = lane >> 2, tg = lane & 3;
    const int r0 = wid * 16 + gid;
    const int r1 = r0 + 8;

    const float* qb = g_q + ((size_t)bh * SEQ + i0) * HDIM;
    const float* kb = g_k + (size_t)bh * SEQ * HDIM;
    const float* vb = g_v + (size_t)bh * SEQ * HDIM;

    // stage Q (already tf32-valued)
    for (int i = tid; i < 128 * 16; i += 256) {
        int row = i >> 4, c4 = (i & 15) * 4;
        *(float4*)&QP[row][c4] = *(const float4*)&qb[(size_t)row * HDIM + c4];
    }
    __syncthreads();

    // Q fragments to registers (held across the whole key loop)
    float qa[8][4];
#pragma unroll
    for (int ks = 0; ks < 8; ks++) {
        qa[ks][0] = QP[r0][ks * 8 + tg];
        qa[ks][1] = QP[r1][ks * 8 + tg];
        qa[ks][2] = QP[r0][ks * 8 + tg + 4];
        qa[ks][3] = QP[r1][ks * 8 + tg + 4];
    }
    const int gi0 = i0 + r0, gi1 = i0 + r1;
    const bool qok0 = (gi0 == 0) || (mask[(size_t)b * (SEQ - 1) + gi0 - 1] != 0);
    const bool qok1 = (gi1 == 0) || (mask[(size_t)b * (SEQ - 1) + gi1 - 1] != 0);

    float m0 = NEGINF, m1 = NEGINF, l0 = 0.f, l1 = 0.f;
    float o[8][4] = {};

    for (int j0 = 0; j0 < SEQ; j0 += 64) {
        __syncthreads();   // protect Ks/Vs (+ QP-as-P) reuse across iterations
        for (int i = tid; i < 64 * 16; i += 256) {
            int row = i >> 4, c4 = (i & 15) * 4;
            *(float4*)&Ks[row][c4] = *(const float4*)&kb[(size_t)(j0 + row) * HDIM + c4];
            *(float4*)&Vs[row][c4] = *(const float4*)&vb[(size_t)(j0 + row) * HDIM + c4];
        }
        if (tid < 64) {
            int gj = j0 + tid;
            km[tid] = (gj == 0) ? 1.f : (mask[(size_t)b * (SEQ - 1) + gj - 1] ? 1.f : 0.f);
        }
        __syncthreads();

        // S = Q K^T  (16 rows x 64 keys per warp)
        float s[8][4] = {};
#pragma unroll
        for (int ks = 0; ks < 8; ks++) {
#pragma unroll
            for (int ni = 0; ni < 8; ni++) {
                float bf[2] = { Ks[ni * 8 + gid][ks * 8 + tg],
                                Ks[ni * 8 + gid][ks * 8 + tg + 4] };
                mma_tf32_16x8x8(s[ni], qa[ks], bf);
            }
        }

        // mask + scale + row max
        float rmax0 = NEGINF, rmax1 = NEGINF;
#pragma unroll
        for (int ni = 0; ni < 8; ni++) {
            bool k0ok = km[ni * 8 + 2 * tg] != 0.f;
            bool k1ok = km[ni * 8 + 2 * tg + 1] != 0.f;
            s[ni][0] = (qok0 && k0ok) ? s[ni][0] * SCALE : MASKV;
            s[ni][1] = (qok0 && k1ok) ? s[ni][1] * SCALE : MASKV;
            s[ni][2] = (qok1 && k0ok) ? s[ni][2] * SCALE : MASKV;
            s[ni][3] = (qok1 && k1ok) ? s[ni][3] * SCALE : MASKV;
            rmax0 = fmaxf(rmax0, fmaxf(s[ni][0], s[ni][1]));
            rmax1 = fmaxf(rmax1, fmaxf(s[ni][2], s[ni][3]));
        }
        rmax0 = fmaxf(rmax0, __shfl_xor_sync(0xffffffffu, rmax0, 1));
        rmax0 = fmaxf(rmax0, __shfl_xor_sync(0xffffffffu, rmax0, 2));
        rmax1 = fmaxf(rmax1, __shfl_xor_sync(0xffffffffu, rmax1, 1));
        rmax1 = fmaxf(rmax1, __shfl_xor_sync(0xffffffffu, rmax1, 2));

        float nm0 = fmaxf(m0, rmax0), nm1 = fmaxf(m1, rmax1);
        float fac0 = __expf(m0 - nm0), fac1 = __expf(m1 - nm1);
        m0 = nm0; m1 = nm1;

        // P = exp(S - m), tf32-rounded; sum rows; stage to smem (Q overlay)
        float sum0 = 0.f, sum1 = 0.f;
#pragma unroll
        for (int ni = 0; ni < 8; ni++) {
            float p0 = tf32_rna(__expf(s[ni][0] - m0));
            float p1 = tf32_rna(__expf(s[ni][1] - m0));
            float p2 = tf32_rna(__expf(s[ni][2] - m1));
            float p3 = tf32_rna(__expf(s[ni][3] - m1));
            sum0 += p0 + p1; sum1 += p2 + p3;
            QP[r0][ni * 8 + 2 * tg]     = p0;
            QP[r0][ni * 8 + 2 * tg + 1] = p1;
            QP[r1][ni * 8 + 2 * tg]     = p2;
            QP[r1][ni * 8 + 2 * tg + 1] = p3;
        }
        sum0 += __shfl_xor_sync(0xffffffffu, sum0, 1);
        sum0 += __shfl_xor_sync(0xffffffffu, sum0, 2);
        sum1 += __shfl_xor_sync(0xffffffffu, sum1, 1);
        sum1 += __shfl_xor_sync(0xffffffffu, sum1, 2);
        l0 = l0 * fac0 + sum0;
        l1 = l1 * fac1 + sum1;

#pragma unroll
        for (int ni = 0; ni < 8; ni++) {
            o[ni][0] *= fac0; o[ni][1] *= fac0;
            o[ni][2] *= fac1; o[ni][3] *= fac1;
        }
        __syncwarp();   // P writes visible to the whole warp before PV reads

        // O += P V   (k-dim = 64 keys)
#pragma unroll
        for (int ks = 0; ks < 8; ks++) {
            float pa[4] = { QP[r0][ks * 8 + tg], QP[r1][ks * 8 + tg],
                            QP[r0][ks * 8 + tg + 4], QP[r1][ks * 8 + tg + 4] };
#pragma unroll
            for (int ni = 0; ni < 8; ni++) {
                float bf[2] = { Vs[ks * 8 + tg][ni * 8 + gid],
                                Vs[ks * 8 + tg + 4][ni * 8 + gid] };
                mma_tf32_16x8x8(o[ni], pa, bf);
            }
        }
        // next-iteration reuse protected by the loop-top __syncthreads
    }

    // normalize + write (tf32-rounded: feeds the cp.async out GEMM)
    float inv0 = 1.f / l0, inv1 = 1.f / l1;
    size_t row0 = (size_t)b * SEQ + i0 + r0;
    size_t row1 = (size_t)b * SEQ + i0 + r1;
#pragma unroll
    for (int ni = 0; ni < 8; ni++) {
        float2 v0 = { tf32_rna(o[ni][0] * inv0), tf32_rna(o[ni][1] * inv0) };
        float2 v1 = { tf32_rna(o[ni][2] * inv1), tf32_rna(o[ni][3] * inv1) };
        *(float2*)&g_attn[row0 * DIM + h * HDIM + ni * 8 + 2 * tg] = v0;
        *(float2*)&g_attn[row1 * DIM + h * HDIM + ni * 8 + 2 * tg] = v1;
    }
}

// ---------------------------------------------------------------------------
extern "C" void kernel_launch(void* const* d_in, const int* in_sizes, int n_in,
                              void* d_out, int out_size)
{
    const float* x    = (const float*)d_in[0];
    const int*   mask = (const int*)d_in[1];     // bool widened to int32 by harness
    const float* pos  = (const float*)d_in[2];
    const float* Wqk  = (const float*)d_in[3];
    const float* Wv   = (const float*)d_in[4];
    const float* Wout = (const float*)d_in[5];
    const float* bout = (const float*)d_in[6];
    float*       out  = (float*)d_out;

    cudaFuncSetAttribute(qkv_gemm_kernel, cudaFuncAttributeMaxDynamicSharedMemorySize,
                         GEMM_SMEM_BYTES);
    cudaFuncSetAttribute(out_gemm_kernel, cudaFuncAttributeMaxDynamicSharedMemorySize,
                         GEMM_SMEM_BYTES);
    cudaFuncSetAttribute(attn_kernel, cudaFuncAttributeMaxDynamicSharedMemorySize,
                         ATT_SMEM_BYTES);

    float* d_xr; float* d_wqkr; float* d_wvr; float* d_woutr;
    cudaGetSymbolAddress((void**)&d_xr,    g_xr);
    cudaGetSymbolAddress((void**)&d_wqkr,  g_wqkr);
    cudaGetSymbolAddress((void**)&d_wvr,   g_wvr);
    cudaGetSymbolAddress((void**)&d_woutr, g_woutr);

    {   // prep: round inputs to tf32 once
        int n4;
        n4 = MROWS * DIM / 4;
        round_kernel<<<(n4 + 255) / 256, 256>>>((const float4*)x, (float4*)d_xr, n4);
        n4 = 2 * DIM * DIM / 4;
        round_kernel<<<(n4 + 255) / 256, 256>>>((const float4*)Wqk, (float4*)d_wqkr, n4);
        n4 = DIM * DIM / 4;
        round_kernel<<<(n4 + 255) / 256, 256>>>((const float4*)Wv, (float4*)d_wvr, n4);
        round_kernel<<<(n4 + 255) / 256, 256>>>((const float4*)Wout, (float4*)d_woutr, n4);
    }
    {   // QKV projection: M=8192, N=3072
        dim3 grid(QKVN / 128, MROWS / 128);
        qkv_gemm_kernel<<<grid, 256, GEMM_SMEM_BYTES>>>(pos);
    }
    {   // Attention: 8 row-tiles x 128 (b,h) pairs
        dim3 grid(SEQ / 128, BATCH * HEADS);
        attn_kernel<<<grid, 256, ATT_SMEM_BYTES>>>(mask);
    }
    {   // Output projection: M=8192, N=1024
        dim3 grid(DIM / 128, MROWS / 128);
        out_gemm_kernel<<<grid, 256, GEMM_SMEM_BYTES>>>(bout, out);
    }
}

// round 5
// speedup vs baseline: 3.7752x; 1.1009x over previous
#include <cuda_runtime.h>
#include <cuda_bf16.h>
#include <cstddef>
#include <cstdint>

// Problem constants
#define BATCH 8
#define SEQ   1024
#define DIM   1024
#define HEADS 16
#define HDIM  64
#define MROWS (BATCH * SEQ)          // 8192
#define QKVN  (3 * DIM)              // 3072
#define SCALE 0.03125f               // DIM^-0.5 = 1/32
#define MASKV (-3.402823466e38f)
#define NEGINF (-__int_as_float(0x7f800000) * 1.0f)

// Scratch (static device globals: allocation-free rule)
__device__ float g_q[BATCH * HEADS * SEQ * HDIM];     // [b,h,n,d]  (tf32-rounded)
__device__ float g_k[BATCH * HEADS * SEQ * HDIM];
__device__ float g_v[BATCH * HEADS * SEQ * HDIM];
__device__ float g_attn[BATCH * SEQ * DIM];           // [b,n,h*d]  (tf32-rounded)
// tf32-rounded input copies (rounding hoisted out of GEMM hot loops)
__device__ float g_xr[MROWS * DIM];
__device__ float g_wqkr[2 * DIM * DIM];
__device__ float g_wvr[DIM * DIM];
__device__ float g_woutr[DIM * DIM];

// ---------------------------------------------------------------------------
// helpers
// ---------------------------------------------------------------------------
__device__ __forceinline__ float tf32_rna(float x) {
    uint32_t u;
    asm("cvt.rna.tf32.f32 %0, %1;" : "=r"(u) : "f"(x));
    return __uint_as_float(u);
}

__device__ __forceinline__ void mma_tf32_16x8x8(float* c, const float* a, const float* b) {
    asm volatile(
        "mma.sync.aligned.m16n8k8.row.col.f32.tf32.tf32.f32 "
        "{%0,%1,%2,%3}, {%4,%5,%6,%7}, {%8,%9}, {%0,%1,%2,%3};"
        : "+f"(c[0]), "+f"(c[1]), "+f"(c[2]), "+f"(c[3])
        : "r"(__float_as_uint(a[0])), "r"(__float_as_uint(a[1])),
          "r"(__float_as_uint(a[2])), "r"(__float_as_uint(a[3])),
          "r"(__float_as_uint(b[0])), "r"(__float_as_uint(b[1])));
}

__device__ __forceinline__ void cp16(void* smem, const void* g) {
    uint32_t s = (uint32_t)__cvta_generic_to_shared(smem);
    asm volatile("cp.async.cg.shared.global [%0], [%1], 16;" :: "r"(s), "l"(g));
}
__device__ __forceinline__ void cp_commit() {
    asm volatile("cp.async.commit_group;");
}

// ---------------------------------------------------------------------------
// Kernel 0: round fp32 -> tf32-valued fp32 (vectorized)
// ---------------------------------------------------------------------------
__global__ __launch_bounds__(256) void round_kernel(
    const float4* __restrict__ src, float4* __restrict__ dst, int n4)
{
    int i = blockIdx.x * 256 + threadIdx.x;
    if (i < n4) {
        float4 v = src[i];
        v.x = tf32_rna(v.x); v.y = tf32_rna(v.y);
        v.z = tf32_rna(v.z); v.w = tf32_rna(v.w);
        dst[i] = v;
    }
}

// ---------------------------------------------------------------------------
// tf32 GEMM core, cp.async 2-stage pipeline. 128x128 tile, K-tile 32,
// 256 threads, 8 warps (2M x 4N), warp tile 64x32 via m16n8k8.
// Inputs must already be tf32-valued.
// ---------------------------------------------------------------------------
#define TPAD 36   // row stride 144 B (16B-aligned, bank-permuting)

struct GemmAcc { float acc[4][4][4]; };

__device__ __forceinline__ void gemm_core_async(
    const float* __restrict__ Abase, const float* __restrict__ B0,
    const float* __restrict__ B1, int bm, int bn, bool splitB,
    float* sm, GemmAcc& g)
{
    // layout: As[2][128][TPAD], Bs[2][128][TPAD]
    float (*As)[128][TPAD] = (float(*)[128][TPAD])sm;
    float (*Bs)[128][TPAD] = (float(*)[128][TPAD])(sm + 2 * 128 * TPAD);

    const int tid = threadIdx.x;
    const int lane = tid & 31;
    const int wid = tid >> 5;
    const int gid = lane >> 2, tg = lane & 3;
    const int wm = (wid & 1) * 64;
    const int wn = (wid >> 1) * 32;

#pragma unroll
    for (int mi = 0; mi < 4; mi++)
#pragma unroll
        for (int ni = 0; ni < 4; ni++)
#pragma unroll
            for (int r = 0; r < 4; r++) g.acc[mi][ni][r] = 0.f;

    auto load_tiles = [&](int st, int k0) {
#pragma unroll
        for (int i = tid; i < 128 * 8; i += 256) {
            int row = i >> 3, c4 = (i & 7) * 4;
            cp16(&As[st][row][c4], &Abase[(size_t)(bm + row) * DIM + k0 + c4]);
        }
#pragma unroll
        for (int i = tid; i < 128 * 8; i += 256) {
            int row = i >> 3, c4 = (i & 7) * 4;
            int gn = bn + row;
            const float* Brow = (splitB && gn >= 2 * DIM)
                                ? B1 + (size_t)(gn - 2 * DIM) * DIM
                                : B0 + (size_t)gn * DIM;
            cp16(&Bs[st][row][c4], &Brow[k0 + c4]);
        }
    };

    load_tiles(0, 0);
    cp_commit();

    const int NT = DIM / 32;  // 32
    for (int it = 0; it < NT; it++) {
        int cur = it & 1;
        if (it + 1 < NT) {
            load_tiles(cur ^ 1, (it + 1) * 32);
            cp_commit();
            asm volatile("cp.async.wait_group 1;");
        } else {
            asm volatile("cp.async.wait_group 0;");
        }
        __syncthreads();

#pragma unroll
        for (int ks = 0; ks < 32; ks += 8) {
            float a[4][4];
#pragma unroll
            for (int mi = 0; mi < 4; mi++) {
                int r0 = wm + mi * 16 + gid;
                a[mi][0] = As[cur][r0][ks + tg];
                a[mi][1] = As[cur][r0 + 8][ks + tg];
                a[mi][2] = As[cur][r0][ks + tg + 4];
                a[mi][3] = As[cur][r0 + 8][ks + tg + 4];
            }
            float b[4][2];
#pragma unroll
            for (int ni = 0; ni < 4; ni++) {
                int n0 = wn + ni * 8 + gid;
                b[ni][0] = Bs[cur][n0][ks + tg];
                b[ni][1] = Bs[cur][n0][ks + tg + 4];
            }
#pragma unroll
            for (int mi = 0; mi < 4; mi++)
#pragma unroll
                for (int ni = 0; ni < 4; ni++)
                    mma_tf32_16x8x8(g.acc[mi][ni], a[mi], b[ni]);
        }
        __syncthreads();
    }
}

#define GEMM_SMEM_BYTES (4 * 128 * TPAD * 4)   // 73728

// ---------------------------------------------------------------------------
// Kernel 1: fused QKV projection. Epilogue adds pos (fp32), rounds result to
// tf32 (feeds attention MMAs), scatters to [b,h,n,d].
// ---------------------------------------------------------------------------
__global__ __launch_bounds__(256) void qkv_gemm_kernel(const float* __restrict__ pos)
{
    extern __shared__ float sm[];
    const int bm = blockIdx.y * 128;
    const int bn = blockIdx.x * 128;
    const int lane = threadIdx.x & 31;
    const int wid = threadIdx.x >> 5;
    const int gid = lane >> 2, tg = lane & 3;
    const int wm = (wid & 1) * 64;
    const int wn = (wid >> 1) * 32;

    GemmAcc g;
    gemm_core_async(g_xr, g_wqkr, g_wvr, bm, bn, true, sm, g);

#pragma unroll
    for (int mi = 0; mi < 4; mi++) {
#pragma unroll
        for (int ni = 0; ni < 4; ni++) {
#pragma unroll
            for (int r = 0; r < 4; r++) {
                int m = bm + wm + mi * 16 + gid + ((r >= 2) ? 8 : 0);
                int gn = bn + wn + ni * 8 + 2 * tg + (r & 1);
                int b = m >> 10, row = m & 1023;
                float val = g.acc[mi][ni][r];
                if (gn < DIM) {
                    int c = gn, h = c >> 6, d = c & 63;
                    val = tf32_rna(val + pos[(size_t)m * DIM + c]);
                    g_q[(((size_t)b * HEADS + h) * SEQ + row) * HDIM + d] = val;
                } else if (gn < 2 * DIM) {
                    int c = gn - DIM, h = c >> 6, d = c & 63;
                    val = tf32_rna(val + pos[(size_t)m * DIM + c]);
                    g_k[(((size_t)b * HEADS + h) * SEQ + row) * HDIM + d] = val;
                } else {
                    int c = gn - 2 * DIM, h = c >> 6, d = c & 63;
                    g_v[(((size_t)b * HEADS + h) * SEQ + row) * HDIM + d] = tf32_rna(val);
                }
            }
        }
    }
}

// ---------------------------------------------------------------------------
// Kernel 3: output projection. out = g_attn @ W_out^T + b_out (fp32 epilogue)
// ---------------------------------------------------------------------------
__global__ __launch_bounds__(256) void out_gemm_kernel(
    const float* __restrict__ bout, float* __restrict__ out)
{
    extern __shared__ float sm[];
    const int bm = blockIdx.y * 128;
    const int bn = blockIdx.x * 128;
    const int lane = threadIdx.x & 31;
    const int wid = threadIdx.x >> 5;
    const int gid = lane >> 2, tg = lane & 3;
    const int wm = (wid & 1) * 64;
    const int wn = (wid >> 1) * 32;

    GemmAcc g;
    gemm_core_async(g_attn, g_woutr, nullptr, bm, bn, false, sm, g);

#pragma unroll
    for (int mi = 0; mi < 4; mi++) {
#pragma unroll
        for (int ni = 0; ni < 4; ni++) {
#pragma unroll
            for (int r = 0; r < 4; r++) {
                int m = bm + wm + mi * 16 + gid + ((r >= 2) ? 8 : 0);
                int gn = bn + wn + ni * 8 + 2 * tg + (r & 1);
                out[(size_t)m * DIM + gn] = g.acc[mi][ni][r] + bout[gn];
            }
        }
    }
}

// ---------------------------------------------------------------------------
// Kernel 2: tensor-core flash attention with cp.async double-buffered K/V.
// 128 query rows per CTA, 8 warps, each owns 16 rows; j-tiles of 64 keys.
// Q fragments register-resident. S and PV via m16n8k8 tf32. Online softmax in
// registers (quad shfl reduce). P staged through smem overlaid on the dead Q
// tile (warp-private rows). Ks stride 68 (bank 4*gid+tg perm), Vs stride 72
// (bank 8*tg+gid perm) -> both fragment patterns conflict-free.
// ---------------------------------------------------------------------------
#define AKPAD 68
#define AVPAD 72
#define ATT_SMEM_FLOATS (128 * AKPAD + 2 * 64 * AKPAD + 2 * 64 * AVPAD + 2 * 64)
#define ATT_SMEM_BYTES  (ATT_SMEM_FLOATS * 4)   // 107008

__global__ __launch_bounds__(256) void attn_kernel(const int* __restrict__ mask)
{
    extern __shared__ float sm[];
    float (*QP)[AKPAD]  = (float(*)[AKPAD])sm;                       // Q tile, later P
    float (*KsB)[AKPAD] = (float(*)[AKPAD])(sm + 128 * AKPAD);      // [2*64][AKPAD]
    float (*VsB)[AVPAD] = (float(*)[AVPAD])(sm + 128 * AKPAD + 2 * 64 * AKPAD);
    float* kmB = sm + 128 * AKPAD + 2 * 64 * AKPAD + 2 * 64 * AVPAD; // [2][64]

    const int bh = blockIdx.y;
    const int b = bh >> 4, h = bh & 15;
    const int i0 = blockIdx.x * 128;
    const int tid = threadIdx.x;
    const int lane = tid & 31, wid = tid >> 5;
    const int gid = lane >> 2, tg = lane & 3;
    const int r0 = wid * 16 + gid;
    const int r1 = r0 + 8;

    const float* qb = g_q + ((size_t)bh * SEQ + i0) * HDIM;
    const float* kb = g_k + (size_t)bh * SEQ * HDIM;
    const float* vb = g_v + (size_t)bh * SEQ * HDIM;

    auto load_kv = [&](int st, int j0) {
        float (*K)[AKPAD] = KsB + st * 64;
        float (*V)[AVPAD] = VsB + st * 64;
#pragma unroll
        for (int i = tid; i < 64 * 16; i += 256) {
            int row = i >> 4, c4 = (i & 15) * 4;
            cp16(&K[row][c4], &kb[(size_t)(j0 + row) * HDIM + c4]);
            cp16(&V[row][c4], &vb[(size_t)(j0 + row) * HDIM + c4]);
        }
    };
    auto load_km = [&](int st, int j0) {
        if (tid < 64) {
            int gj = j0 + tid;
            kmB[st * 64 + tid] =
                (gj == 0) ? 1.f : (mask[(size_t)b * (SEQ - 1) + gj - 1] ? 1.f : 0.f);
        }
    };

    // kick off tile 0 K/V while we stage Q
    load_kv(0, 0);
    cp_commit();
    load_km(0, 0);

    // stage Q (already tf32-valued)
    for (int i = tid; i < 128 * 16; i += 256) {
        int row = i >> 4, c4 = (i & 15) * 4;
        *(float4*)&QP[row][c4] = *(const float4*)&qb[(size_t)row * HDIM + c4];
    }
    __syncthreads();

    // Q fragments to registers (held across the whole key loop)
    float qa[8][4];
#pragma unroll
    for (int ks = 0; ks < 8; ks++) {
        qa[ks][0] = QP[r0][ks * 8 + tg];
        qa[ks][1] = QP[r1][ks * 8 + tg];
        qa[ks][2] = QP[r0][ks * 8 + tg + 4];
        qa[ks][3] = QP[r1][ks * 8 + tg + 4];
    }
    const int gi0 = i0 + r0, gi1 = i0 + r1;
    const bool qok0 = (gi0 == 0) || (mask[(size_t)b * (SEQ - 1) + gi0 - 1] != 0);
    const bool qok1 = (gi1 == 0) || (mask[(size_t)b * (SEQ - 1) + gi1 - 1] != 0);

    float m0 = NEGINF, m1 = NEGINF, l0 = 0.f, l1 = 0.f;
    float o[8][4] = {};

    const int NT = SEQ / 64;   // 16
    for (int it = 0; it < NT; it++) {
        const int cur = it & 1;
        if (it + 1 < NT) {
            load_kv(cur ^ 1, (it + 1) * 64);
            cp_commit();
            load_km(cur ^ 1, (it + 1) * 64);
            asm volatile("cp.async.wait_group 1;");
        } else {
            asm volatile("cp.async.wait_group 0;");
        }
        __syncthreads();

        float (*Ks)[AKPAD] = KsB + cur * 64;
        float (*Vs)[AVPAD] = VsB + cur * 64;
        const float* km = kmB + cur * 64;

        // S = Q K^T  (16 rows x 64 keys per warp)
        float s[8][4] = {};
#pragma unroll
        for (int ks = 0; ks < 8; ks++) {
#pragma unroll
            for (int ni = 0; ni < 8; ni++) {
                float bf[2] = { Ks[ni * 8 + gid][ks * 8 + tg],
                                Ks[ni * 8 + gid][ks * 8 + tg + 4] };
                mma_tf32_16x8x8(s[ni], qa[ks], bf);
            }
        }

        // mask + scale + row max
        float rmax0 = NEGINF, rmax1 = NEGINF;
#pragma unroll
        for (int ni = 0; ni < 8; ni++) {
            bool k0ok = km[ni * 8 + 2 * tg] != 0.f;
            bool k1ok = km[ni * 8 + 2 * tg + 1] != 0.f;
            s[ni][0] = (qok0 && k0ok) ? s[ni][0] * SCALE : MASKV;
            s[ni][1] = (qok0 && k1ok) ? s[ni][1] * SCALE : MASKV;
            s[ni][2] = (qok1 && k0ok) ? s[ni][2] * SCALE : MASKV;
            s[ni][3] = (qok1 && k1ok) ? s[ni][3] * SCALE : MASKV;
            rmax0 = fmaxf(rmax0, fmaxf(s[ni][0], s[ni][1]));
            rmax1 = fmaxf(rmax1, fmaxf(s[ni][2], s[ni][3]));
        }
        rmax0 = fmaxf(rmax0, __shfl_xor_sync(0xffffffffu, rmax0, 1));
        rmax0 = fmaxf(rmax0, __shfl_xor_sync(0xffffffffu, rmax0, 2));
        rmax1 = fmaxf(rmax1, __shfl_xor_sync(0xffffffffu, rmax1, 1));
        rmax1 = fmaxf(rmax1, __shfl_xor_sync(0xffffffffu, rmax1, 2));

        float nm0 = fmaxf(m0, rmax0), nm1 = fmaxf(m1, rmax1);
        float fac0 = __expf(m0 - nm0), fac1 = __expf(m1 - nm1);
        m0 = nm0; m1 = nm1;

        // P = exp(S - m), tf32-rounded; sum rows; stage to smem (Q overlay)
        float sum0 = 0.f, sum1 = 0.f;
#pragma unroll
        for (int ni = 0; ni < 8; ni++) {
            float p0 = tf32_rna(__expf(s[ni][0] - m0));
            float p1 = tf32_rna(__expf(s[ni][1] - m0));
            float p2 = tf32_rna(__expf(s[ni][2] - m1));
            float p3 = tf32_rna(__expf(s[ni][3] - m1));
            sum0 += p0 + p1; sum1 += p2 + p3;
            QP[r0][ni * 8 + 2 * tg]     = p0;
            QP[r0][ni * 8 + 2 * tg + 1] = p1;
            QP[r1][ni * 8 + 2 * tg]     = p2;
            QP[r1][ni * 8 + 2 * tg + 1] = p3;
        }
        sum0 += __shfl_xor_sync(0xffffffffu, sum0, 1);
        sum0 += __shfl_xor_sync(0xffffffffu, sum0, 2);
        sum1 += __shfl_xor_sync(0xffffffffu, sum1, 1);
        sum1 += __shfl_xor_sync(0xffffffffu, sum1, 2);
        l0 = l0 * fac0 + sum0;
        l1 = l1 * fac1 + sum1;

#pragma unroll
        for (int ni = 0; ni < 8; ni++) {
            o[ni][0] *= fac0; o[ni][1] *= fac0;
            o[ni][2] *= fac1; o[ni][3] *= fac1;
        }
        __syncwarp();   // P writes visible to the whole warp before PV reads

        // O += P V   (k-dim = 64 keys)
#pragma unroll
        for (int ks = 0; ks < 8; ks++) {
            float pa[4] = { QP[r0][ks * 8 + tg], QP[r1][ks * 8 + tg],
                            QP[r0][ks * 8 + tg + 4], QP[r1][ks * 8 + tg + 4] };
#pragma unroll
            for (int ni = 0; ni < 8; ni++) {
                float bf[2] = { Vs[ks * 8 + tg][ni * 8 + gid],
                                Vs[ks * 8 + tg + 4][ni * 8 + gid] };
                mma_tf32_16x8x8(o[ni], pa, bf);
            }
        }
        __syncthreads();   // all reads done before next iter's cp.async overwrites
    }

    // normalize + write (tf32-rounded: feeds the cp.async out GEMM)
    float inv0 = 1.f / l0, inv1 = 1.f / l1;
    size_t row0 = (size_t)b * SEQ + i0 + r0;
    size_t row1 = (size_t)b * SEQ + i0 + r1;
#pragma unroll
    for (int ni = 0; ni < 8; ni++) {
        float2 v0 = { tf32_rna(o[ni][0] * inv0), tf32_rna(o[ni][1] * inv0) };
        float2 v1 = { tf32_rna(o[ni][2] * inv1), tf32_rna(o[ni][3] * inv1) };
        *(float2*)&g_attn[row0 * DIM + h * HDIM + ni * 8 + 2 * tg] = v0;
        *(float2*)&g_attn[row1 * DIM + h * HDIM + ni * 8 + 2 * tg] = v1;
    }
}

// ---------------------------------------------------------------------------
extern "C" void kernel_launch(void* const* d_in, const int* in_sizes, int n_in,
                              void* d_out, int out_size)
{
    const float* x    = (const float*)d_in[0];
    const int*   mask = (const int*)d_in[1];     // bool widened to int32 by harness
    const float* pos  = (const float*)d_in[2];
    const float* Wqk  = (const float*)d_in[3];
    const float* Wv   = (const float*)d_in[4];
    const float* Wout = (const float*)d_in[5];
    const float* bout = (const float*)d_in[6];
    float*       out  = (float*)d_out;

    cudaFuncSetAttribute(qkv_gemm_kernel, cudaFuncAttributeMaxDynamicSharedMemorySize,
                         GEMM_SMEM_BYTES);
    cudaFuncSetAttribute(out_gemm_kernel, cudaFuncAttributeMaxDynamicSharedMemorySize,
                         GEMM_SMEM_BYTES);
    cudaFuncSetAttribute(attn_kernel, cudaFuncAttributeMaxDynamicSharedMemorySize,
                         ATT_SMEM_BYTES);

    float* d_xr; float* d_wqkr; float* d_wvr; float* d_woutr;
    cudaGetSymbolAddress((void**)&d_xr,    g_xr);
    cudaGetSymbolAddress((void**)&d_wqkr,  g_wqkr);
    cudaGetSymbolAddress((void**)&d_wvr,   g_wvr);
    cudaGetSymbolAddress((void**)&d_woutr, g_woutr);

    {   // prep: round inputs to tf32 once
        int n4;
        n4 = MROWS * DIM / 4;
        round_kernel<<<(n4 + 255) / 256, 256>>>((const float4*)x, (float4*)d_xr, n4);
        n4 = 2 * DIM * DIM / 4;
        round_kernel<<<(n4 + 255) / 256, 256>>>((const float4*)Wqk, (float4*)d_wqkr, n4);
        n4 = DIM * DIM / 4;
        round_kernel<<<(n4 + 255) / 256, 256>>>((const float4*)Wv, (float4*)d_wvr, n4);
        round_kernel<<<(n4 + 255) / 256, 256>>>((const float4*)Wout, (float4*)d_woutr, n4);
    }
    {   // QKV projection: M=8192, N=3072
        dim3 grid(QKVN / 128, MROWS / 128);
        qkv_gemm_kernel<<<grid, 256, GEMM_SMEM_BYTES>>>(pos);
    }
    {   // Attention: 8 row-tiles x 128 (b,h) pairs
        dim3 grid(SEQ / 128, BATCH * HEADS);
        attn_kernel<<<grid, 256, ATT_SMEM_BYTES>>>(mask);
    }
    {   // Output projection: M=8192, N=1024
        dim3 grid(DIM / 128, MROWS / 128);
        out_gemm_kernel<<<grid, 256, GEMM_SMEM_BYTES>>>(bout, out);
    }
}